// round 5
// baseline (speedup 1.0000x reference)
#include <cuda_runtime.h>

#define RPB 512   // rows per block
#define TPB 256   // 2 rows per thread

__device__ __forceinline__ float fsqrt_ap(float x) {
    float r; asm("sqrt.approx.f32 %0, %1;" : "=f"(r) : "f"(x)); return r;
}
__device__ __forceinline__ float frsqrt_ap(float x) {
    float r; asm("rsqrt.approx.f32 %0, %1;" : "=f"(r) : "f"(x)); return r;
}
__device__ __forceinline__ float frcp_ap(float x) {
    float r; asm("rcp.approx.f32 %0, %1;" : "=f"(r) : "f"(x)); return r;
}

__global__ __launch_bounds__(TPB, 6) void vp_lattice_kernel(
    const float* __restrict__ lt_g,
    const float* __restrict__ l0_g,
    const float* __restrict__ pl_g,
    const float* __restrict__ alpha_bars,
    const float* __restrict__ betas,
    const float* __restrict__ sigmas,
    const float* __restrict__ zn_g,
    const int*   __restrict__ traw,
    float* __restrict__ out_g,
    int B)
{
    __shared__ float s_pl   [RPB * 9];
    __shared__ float s_vec  [RPB * 6];
    __shared__ float s_coef [RPB];
    __shared__ float s_scale[RPB];
    __shared__ float s_zm   [RPB];
    __shared__ int   s_tstride;

    const int tid = threadIdx.x;
    const long long base = (long long)blockIdx.x * RPB;
    const int nrows = (int)min((long long)RPB, (long long)B - base);

    // ---- detect t dtype once per block (int64 vs int32, little-endian) ----
    if (tid == 0) {
        int acc = traw[1] | traw[3] | traw[5] | traw[7] |
                  traw[9] | traw[11] | traw[13] | traw[15];
        s_tstride = (acc == 0) ? 2 : 1;
    }

    // ---- stage pred_lattice (row-gather access pattern) ----
    if (nrows == RPB) {
        const float4* pl4 = (const float4*)(pl_g + base * 9);
        #pragma unroll
        for (int i = tid; i < RPB * 9 / 4; i += TPB)
            ((float4*)s_pl)[i] = __ldcs(&pl4[i]);
    } else {
        for (int i = tid; i < nrows * 9; i += TPB)
            s_pl[i] = pl_g[base * 9 + i];
    }
    __syncthreads();

    // ---- per-row math: 2 independent rows per thread for chain ILP ----
    {
        const int tstride = s_tstride;
        #pragma unroll
        for (int half = 0; half < 2; half++) {
            // NOTE: both lanes unrolled; independent chains interleave.
        }
        float m00[2], m11[2], m22[2], m01[2], m02[2], m12[2];
        float e1[2], e2c[2], sc[2], sa[2], sb[2];
        int   tt[2];
        bool  act[2];

        #pragma unroll
        for (int h = 0; h < 2; h++) {
            const int row = tid + h * TPB;
            act[h] = (row < nrows);
            if (!act[h]) { tt[h]=0; m00[h]=m11[h]=m22[h]=1; m01[h]=m02[h]=m12[h]=0; }
            else {
                const long long g = base + row;
                tt[h] = __ldg(&traw[g * tstride]);
                const float a0 = s_pl[row*9+0], a1 = s_pl[row*9+1], a2 = s_pl[row*9+2];
                const float a3 = s_pl[row*9+3], a4 = s_pl[row*9+4], a5 = s_pl[row*9+5];
                const float a6 = s_pl[row*9+6], a7 = s_pl[row*9+7], a8 = s_pl[row*9+8];
                m00[h] = a0*a0 + a3*a3 + a6*a6;
                m11[h] = a1*a1 + a4*a4 + a7*a7;
                m22[h] = a2*a2 + a5*a5 + a8*a8;
                m01[h] = a0*a1 + a3*a4 + a6*a7;
                m02[h] = a0*a2 + a3*a5 + a6*a8;
                m12[h] = a1*a2 + a4*a5 + a7*a8;
            }
        }

        #pragma unroll
        for (int h = 0; h < 2; h++) {
            e1[h] = m00[h] + m11[h] + m22[h];
            const float e2 = (m00[h]*m11[h] - m01[h]*m01[h])
                           + (m00[h]*m22[h] - m02[h]*m02[h])
                           + (m11[h]*m22[h] - m12[h]*m12[h]);
            const float e3 = m00[h]*(m11[h]*m22[h] - m12[h]*m12[h])
                           - m01[h]*(m01[h]*m22[h] - m12[h]*m02[h])
                           + m02[h]*(m01[h]*m12[h] - m11[h]*m02[h]);
            e2c[h] = fmaxf(e2, 0.0f);
            sc[h]  = fsqrt_ap(fmaxf(e3, 0.0f));
        }

        // two interleaved fixed-point chains
        #pragma unroll
        for (int h = 0; h < 2; h++) {
            sb[h] = fsqrt_ap(e2c[h]);
            sa[h] = fsqrt_ap(fmaxf(e1[h] + 2.0f * sb[h], 0.0f));
        }
        #pragma unroll
        for (int it = 0; it < 5; it++) {
            #pragma unroll
            for (int h = 0; h < 2; h++) {
                sb[h] = fsqrt_ap(fmaxf(e2c[h] + 2.0f * sc[h] * sa[h], 0.0f));
                sa[h] = fsqrt_ap(fmaxf(e1[h] + 2.0f * sb[h], 0.0f));
            }
        }

        #pragma unroll
        for (int h = 0; h < 2; h++) {
            if (!act[h]) continue;
            const int row = tid + h * TPB;

            const float n00 = m00[h] + sb[h], n11 = m11[h] + sb[h], n22 = m22[h] + sb[h];
            const float c00 = n11*n22 - m12[h]*m12[h];
            const float c01 = m02[h]*m12[h] - m01[h]*n22;
            const float c02 = m01[h]*m12[h] - n11*m02[h];
            const float c11 = n00*n22 - m02[h]*m02[h];
            const float c12 = m01[h]*m02[h] - n00*m12[h];
            const float c22 = n00*n11 - m01[h]*m01[h];
            const float det = fmaxf(n00*c00 + m01[h]*c01 + m02[h]*c02, 1e-30f);
            const float k   = (sc[h] - sa[h] * sb[h]) * frcp_ap(det);

            s_vec[row*6+0] = sa[h] + k * c00;
            s_vec[row*6+1] =         k * c01;
            s_vec[row*6+2] =         k * c02;
            s_vec[row*6+3] = sa[h] + k * c11;
            s_vec[row*6+4] =         k * c12;
            s_vec[row*6+5] = sa[h] + k * c22;

            const float beta_t  = __ldg(&betas[tt[h]]);
            const float beta_m2 = __ldg(&betas[999]);       // betas[-2], len 1001
            const float alpha   = fmaxf(1.0f - beta_t, 1.0f - beta_m2);
            const float albar   = __ldg(&alpha_bars[tt[h]]);
            const float sigma   = __ldg(&sigmas[tt[h]]);

            s_coef [row] = frsqrt_ap(alpha + 1e-8f);
            s_scale[row] = (1.0f - alpha) * frsqrt_ap(1.0f - albar + 1e-8f);
            s_zm   [row] = (tt[h] > 1) ? sigma : 0.0f;
        }
    }
    __syncthreads();

    // ---- elementwise epilogue: direct coalesced global I/O, 3 float4/thread/array ----
    if (nrows == RPB) {
        const float4* lt4 = (const float4*)(lt_g + base * 6);
        const float4* l04 = (const float4*)(l0_g + base * 6);
        const float4* z4  = (const float4*)(zn_g + base * 6);
        float4*       o4  = (float4*)(out_g + base * 6);
        #pragma unroll
        for (int q = 0; q < 3; q++) {
            const int i = tid + q * TPB;
            const float4 a  = __ldcs(&lt4[i]);
            const float4 b  = __ldcs(&l04[i]);
            const float4 zz = __ldcs(&z4[i]);
            const float av[4] = { a.x, a.y, a.z, a.w };
            const float bv[4] = { b.x, b.y, b.z, b.w };
            const float zv[4] = { zz.x, zz.y, zz.z, zz.w };
            float ov[4];
            const int e0 = i * 4;
            #pragma unroll
            for (int c = 0; c < 4; c++) {
                const int e = e0 + c;
                const int row = e / 6;
                const int kk  = e - row * 6;
                const float v  = s_vec[row*6 + kk];
                const float pn = av[c] - 0.5f * (v + bv[c]);
                ov[c] = s_coef[row] * (av[c] - s_scale[row] * pn)
                      + s_zm[row] * zv[c];
            }
            __stcs(&o4[i], make_float4(ov[0], ov[1], ov[2], ov[3]));
        }
    } else {
        for (int i = tid; i < nrows * 6; i += TPB) {
            const int row = i / 6;
            const int kk  = i - row * 6;
            const float ltv = lt_g[base*6 + i];
            const float pn  = ltv - 0.5f * (s_vec[row*6+kk] + l0_g[base*6 + i]);
            out_g[base*6 + i] = s_coef[row] * (ltv - s_scale[row] * pn)
                              + s_zm[row] * zn_g[base*6 + i];
        }
    }
}

extern "C" void kernel_launch(void* const* d_in, const int* in_sizes, int n_in,
                              void* d_out, int out_size)
{
    const float* lt  = (const float*)d_in[0];
    const float* l0  = (const float*)d_in[1];
    const float* pl  = (const float*)d_in[2];
    const float* ab  = (const float*)d_in[3];
    const float* be  = (const float*)d_in[4];
    const float* si  = (const float*)d_in[5];
    const float* zn  = (const float*)d_in[6];
    const int*   t   = (const int*)d_in[7];
    float* out = (float*)d_out;

    const int B = in_sizes[0] / 6;          // lt is (B, 6)
    const int blocks = (B + RPB - 1) / RPB;

    vp_lattice_kernel<<<blocks, TPB>>>(lt, l0, pl, ab, be, si, zn, t, out, B);
}

// round 6
// speedup vs baseline: 1.3864x; 1.3864x over previous
#include <cuda_runtime.h>

#define RPB 128   // rows per block
#define TPB 128   // 1 row per thread

__device__ __forceinline__ float fsqrt_ap(float x) {
    float r; asm("sqrt.approx.f32 %0, %1;" : "=f"(r) : "f"(x)); return r;
}
__device__ __forceinline__ float frsqrt_ap(float x) {
    float r; asm("rsqrt.approx.f32 %0, %1;" : "=f"(r) : "f"(x)); return r;
}
__device__ __forceinline__ float frcp_ap(float x) {
    float r; asm("rcp.approx.f32 %0, %1;" : "=f"(r) : "f"(x)); return r;
}

__global__ __launch_bounds__(TPB, 16) void vp_lattice_kernel(
    const float* __restrict__ lt_g,
    const float* __restrict__ l0_g,
    const float* __restrict__ pl_g,
    const float* __restrict__ alpha_bars,
    const float* __restrict__ betas,
    const float* __restrict__ sigmas,
    const float* __restrict__ zn_g,
    const int*   __restrict__ traw,
    float* __restrict__ out_g,
    int B)
{
    // s_pl doubles as vec storage after the math phase (vec row aliased
    // into the same 9-float row slot; each thread owns its row, no hazard).
    __shared__ float s_pl   [RPB * 9];
    __shared__ float s_coef [RPB];
    __shared__ float s_scale[RPB];
    __shared__ float s_zm   [RPB];
    __shared__ int   s_tstride;

    const int tid = threadIdx.x;
    const long long base = (long long)blockIdx.x * RPB;
    const int nrows = (int)min((long long)RPB, (long long)B - base);

    // ---- detect t dtype once per block (int64 vs int32, little-endian) ----
    if (tid == 0) {
        int acc = traw[1] | traw[3] | traw[5] | traw[7] |
                  traw[9] | traw[11] | traw[13] | traw[15];
        s_tstride = (acc == 0) ? 2 : 1;
    }

    // ---- stage pred_lattice (row-gather access pattern) ----
    if (nrows == RPB) {
        const float4* pl4 = (const float4*)(pl_g + base * 9);
        #pragma unroll
        for (int i = tid; i < RPB * 9 / 4; i += TPB)
            ((float4*)s_pl)[i] = __ldcs(&pl4[i]);
    } else {
        for (int i = tid; i < nrows * 9; i += TPB)
            s_pl[i] = pl_g[base * 9 + i];
    }
    __syncthreads();

    if (tid < nrows) {
        const int row = tid;
        const long long g = base + row;
        const int tt = __ldg(&traw[g * s_tstride]);

        const float beta_t  = __ldg(&betas[tt]);
        const float beta_m2 = __ldg(&betas[999]);          // betas[-2], len 1001
        const float alpha   = fmaxf(1.0f - beta_t, 1.0f - beta_m2);
        const float albar   = __ldg(&alpha_bars[tt]);
        const float sigma   = __ldg(&sigmas[tt]);

        // ---- A = pred_lattice row (row-major 3x3) ----
        const float a0 = s_pl[row*9+0], a1 = s_pl[row*9+1], a2 = s_pl[row*9+2];
        const float a3 = s_pl[row*9+3], a4 = s_pl[row*9+4], a5 = s_pl[row*9+5];
        const float a6 = s_pl[row*9+6], a7 = s_pl[row*9+7], a8 = s_pl[row*9+8];

        // ---- M = A^T A (symmetric PSD) ----
        const float m00 = a0*a0 + a3*a3 + a6*a6;
        const float m11 = a1*a1 + a4*a4 + a7*a7;
        const float m22 = a2*a2 + a5*a5 + a8*a8;
        const float m01 = a0*a1 + a3*a4 + a6*a7;
        const float m02 = a0*a2 + a3*a5 + a6*a8;
        const float m12 = a1*a2 + a4*a5 + a7*a8;

        // ---- invariants: e1=tr, e2=sum 2x2 minors, e3=det ----
        const float e1 = m00 + m11 + m22;
        const float e2 = (m00*m11 - m01*m01)
                       + (m00*m22 - m02*m02)
                       + (m11*m22 - m12*m12);
        const float e3 = m00*(m11*m22 - m12*m12)
                       - m01*(m01*m22 - m12*m02)
                       + m02*(m01*m12 - m11*m02);

        // ---- elementary symmetric functions of singular values
        //      sc = sqrt(e3);  sa^2 = e1 + 2 sb ;  sb^2 = e2 + 2 sc sa
        //      fixed point, loop gain sc/(sa*sb) <= 1/9 (AM-GM)
        const float sc  = fsqrt_ap(fmaxf(e3, 0.0f));
        const float e2c = fmaxf(e2, 0.0f);
        float sb = fsqrt_ap(e2c);
        float sa = fsqrt_ap(fmaxf(e1 + 2.0f * sb, 0.0f));
        #pragma unroll
        for (int it = 0; it < 4; it++) {
            sb = fsqrt_ap(fmaxf(e2c + 2.0f * sc * sa, 0.0f));
            sa = fsqrt_ap(fmaxf(e1 + 2.0f * sb, 0.0f));
        }

        // ---- U = sqrt(M) = sa*I + k*adj(N),  N = M + sb*I,
        //      k = (sc - sa*sb) / det(N)   (exactly symmetric)
        const float n00 = m00 + sb, n11 = m11 + sb, n22 = m22 + sb;
        const float c00 = n11*n22 - m12*m12;
        const float c01 = m02*m12 - m01*n22;
        const float c02 = m01*m12 - n11*m02;
        const float c11 = n00*n22 - m02*m02;
        const float c12 = m01*m02 - n00*m12;
        const float c22 = n00*n11 - m01*m01;
        const float det = fmaxf(n00*c00 + m01*c01 + m02*c02, 1e-30f);
        const float k   = (sc - sa * sb) * frcp_ap(det);

        // write vec into the (now dead) s_pl row slot
        s_pl[row*9+0] = sa + k * c00;
        s_pl[row*9+1] =      k * c01;
        s_pl[row*9+2] =      k * c02;
        s_pl[row*9+3] = sa + k * c11;
        s_pl[row*9+4] =      k * c12;
        s_pl[row*9+5] = sa + k * c22;

        s_coef [row] = frsqrt_ap(alpha + 1e-8f);
        s_scale[row] = (1.0f - alpha) * frsqrt_ap(1.0f - albar + 1e-8f);
        s_zm   [row] = (tt > 1) ? sigma : 0.0f;
    }
    __syncthreads();

    // ---- elementwise epilogue: direct coalesced global I/O ----
    if (nrows == RPB) {
        const float4* lt4 = (const float4*)(lt_g + base * 6);
        const float4* l04 = (const float4*)(l0_g + base * 6);
        const float4* z4  = (const float4*)(zn_g + base * 6);
        float4*       o4  = (float4*)(out_g + base * 6);
        #pragma unroll
        for (int i = tid; i < RPB * 6 / 4; i += TPB) {
            const float4 a  = __ldcs(&lt4[i]);
            const float4 b  = __ldcs(&l04[i]);
            const float4 zz = __ldcs(&z4[i]);
            const float av[4] = { a.x, a.y, a.z, a.w };
            const float bv[4] = { b.x, b.y, b.z, b.w };
            const float zv[4] = { zz.x, zz.y, zz.z, zz.w };
            float ov[4];
            const int e0 = i * 4;
            #pragma unroll
            for (int c = 0; c < 4; c++) {
                const int e = e0 + c;
                const int row = e / 6;
                const int kk  = e - row * 6;
                const float v  = s_pl[row*9 + kk];     // aliased vec
                const float pn = av[c] - 0.5f * (v + bv[c]);
                ov[c] = s_coef[row] * (av[c] - s_scale[row] * pn)
                      + s_zm[row] * zv[c];
            }
            __stcs(&o4[i], make_float4(ov[0], ov[1], ov[2], ov[3]));
        }
    } else {
        for (int i = tid; i < nrows * 6; i += TPB) {
            const int row = i / 6;
            const int kk  = i - row * 6;
            const float ltv = lt_g[base*6 + i];
            const float pn  = ltv - 0.5f * (s_pl[row*9+kk] + l0_g[base*6 + i]);
            out_g[base*6 + i] = s_coef[row] * (ltv - s_scale[row] * pn)
                              + s_zm[row] * zn_g[base*6 + i];
        }
    }
}

extern "C" void kernel_launch(void* const* d_in, const int* in_sizes, int n_in,
                              void* d_out, int out_size)
{
    const float* lt  = (const float*)d_in[0];
    const float* l0  = (const float*)d_in[1];
    const float* pl  = (const float*)d_in[2];
    const float* ab  = (const float*)d_in[3];
    const float* be  = (const float*)d_in[4];
    const float* si  = (const float*)d_in[5];
    const float* zn  = (const float*)d_in[6];
    const int*   t   = (const int*)d_in[7];
    float* out = (float*)d_out;

    const int B = in_sizes[0] / 6;          // lt is (B, 6)
    const int blocks = (B + RPB - 1) / RPB;

    vp_lattice_kernel<<<blocks, TPB>>>(lt, l0, pl, ab, be, si, zn, t, out, B);
}